// round 14
// baseline (speedup 1.0000x reference)
#include <cuda_runtime.h>
#include <cuda_bf16.h>
#include <math.h>
#include <stdint.h>

#define Bb 128
#define Nn 49
#define Dd 2048
#define H1v 1024
#define H2v 512
#define ROWS (Bb*Nn)
#define TOPKv 20

typedef __nv_bfloat16 bf16;

// ---------------- static scratch ----------------
__device__ alignas(128) bf16 g_x1e[(size_t)ROWS*3*Dd];
__device__ alignas(128) bf16 g_x2e[(size_t)ROWS*3*Dd];
__device__ alignas(128) bf16 g_w0ae[(size_t)H1v*3*Dd];
__device__ alignas(128) bf16 g_w1ae[(size_t)H1v*3*Dd];
__device__ alignas(128) bf16 g_w0be[(size_t)H2v*3*H1v];
__device__ alignas(128) bf16 g_w1be[(size_t)H2v*3*H1v];
__device__ alignas(128) bf16 g_h1ae[(size_t)ROWS*3*H1v];
__device__ alignas(128) bf16 g_h1be[(size_t)ROWS*3*H1v];
__device__ alignas(128) float g_gp1[(size_t)6*ROWS*H1v];
__device__ alignas(128) float g_gp2[(size_t)4*ROWS*H2v];
__device__ alignas(128) float g_h2a[ROWS*H2v], g_h2b[ROWS*H2v];
__device__ alignas(128) float g_s1[ROWS*Dd], g_s2[ROWS*Dd];
__device__ float g_part[(size_t)Bb*Nn*Nn], g_scores[Nn*Nn], g_M[Nn*Nn];
__device__ float g_bnsc[4*Nn], g_bnsh[4*Nn], g_rowsum[2*H2v];
__device__ float g_bnpart[2*Nn*8*2];
__device__ float g_topv[2*Nn*TOPKv];
__device__ int   g_topi[2*Nn*TOPKv];
__device__ float g_fpart[2*ROWS*16*2];

// ---------------- PTX helpers ----------------
__device__ __forceinline__ uint32_t smem_u32(const void* p) {
    uint32_t a;
    asm("{ .reg .u64 t; cvta.to.shared.u64 t, %1; cvt.u32.u64 %0, t; }" : "=r"(a) : "l"(p));
    return a;
}
__device__ __forceinline__ void cp16(uint32_t s, const void* g) {
    asm volatile("cp.async.cg.shared.global [%0], [%1], 16;" :: "r"(s), "l"(g));
}
#define CP_COMMIT() asm volatile("cp.async.commit_group;" ::: "memory")
#define CP_WAIT1()  asm volatile("cp.async.wait_group 1;" ::: "memory")

__device__ __forceinline__ void ldsm_x4(uint32_t (&r)[4], uint32_t a) {
    asm volatile("ldmatrix.sync.aligned.m8n8.x4.shared.b16 {%0,%1,%2,%3}, [%4];"
        : "=r"(r[0]), "=r"(r[1]), "=r"(r[2]), "=r"(r[3]) : "r"(a));
}
__device__ __forceinline__ void hmma(float (&d)[4], const uint32_t (&a)[4], const uint32_t (&b)[2]) {
    asm volatile("mma.sync.aligned.m16n8k16.row.col.f32.bf16.bf16.f32 "
        "{%0,%1,%2,%3},{%4,%5,%6,%7},{%8,%9},{%0,%1,%2,%3};"
        : "+f"(d[0]), "+f"(d[1]), "+f"(d[2]), "+f"(d[3])
        : "r"(a[0]), "r"(a[1]), "r"(a[2]), "r"(a[3]), "r"(b[0]), "r"(b[1]));
}
__device__ __forceinline__ uint32_t packbf2(float a, float b) {
    __nv_bfloat162 t = __floats2bfloat162_rn(a, b);
    return *reinterpret_cast<uint32_t*>(&t);
}

__device__ __forceinline__ float2 blockReduce2(float a, float b) {
    __shared__ float2 sb[8];
    int lane = threadIdx.x & 31, w = threadIdx.x >> 5;
    #pragma unroll
    for (int o = 16; o > 0; o >>= 1) {
        a += __shfl_down_sync(0xffffffffu, a, o);
        b += __shfl_down_sync(0xffffffffu, b, o);
    }
    __syncthreads();
    if (lane == 0) sb[w] = make_float2(a, b);
    __syncthreads();
    int nw = (blockDim.x + 31) >> 5;
    float2 r = make_float2(0.f, 0.f);
    #pragma unroll
    for (int i = 0; i < 8; i++) if (i < nw) { r.x += sb[i].x; r.y += sb[i].y; }
    return r;
}
__device__ __forceinline__ float blockReduceSum(float v) {
    float2 r = blockReduce2(v, 0.f);
    return r.x;
}

// ---------------- fp32 -> ext bf16 (two streams per launch) ----------------
__global__ void cvt_ext3(const float* __restrict__ x0, const float* __restrict__ x1,
                         bf16* __restrict__ y0, bf16* __restrict__ y1,
                         int K4, int n4, int kindA) {
    const float* x = blockIdx.y ? x1 : x0;
    bf16* y = blockIdx.y ? y1 : y0;
    int i = blockIdx.x * blockDim.x + threadIdx.x;
    if (i >= n4) return;
    int row = i / K4, k4 = i - row * K4;
    float4 v = reinterpret_cast<const float4*>(x)[i];
    bf16 h0 = __float2bfloat16(v.x), h1 = __float2bfloat16(v.y);
    bf16 h2 = __float2bfloat16(v.z), h3 = __float2bfloat16(v.w);
    uint2 hw, lw;
    hw.x = packbf2(v.x, v.y); hw.y = packbf2(v.z, v.w);
    lw.x = packbf2(v.x - __bfloat162float(h0), v.y - __bfloat162float(h1));
    lw.y = packbf2(v.z - __bfloat162float(h2), v.w - __bfloat162float(h3));
    bf16* base = y + (size_t)row * (12 * K4) + k4 * 4;
    *reinterpret_cast<uint2*>(base) = hw;
    if (kindA) {
        *reinterpret_cast<uint2*>(base + 4 * K4) = hw;
        *reinterpret_cast<uint2*>(base + 8 * K4) = lw;
    } else {
        *reinterpret_cast<uint2*>(base + 4 * K4) = lw;
        *reinterpret_cast<uint2*>(base + 8 * K4) = hw;
    }
}

// ---------------- HMMA GEMM: 128x256 CTA, split-K, raw fp32 partials ----------------
struct GArgs {
    const bf16 *A, *W;
    float* Cf;
};

#define SUB_BYTES   49152u
#define STAGE_BYTES 98304u

__global__ __launch_bounds__(256, 1)
void hmma_gemm(GArgs ga0, GArgs ga1, int Nc, int Kext, int nstPer, int ksplit)
{
    extern __shared__ char dsm[];
    const int stream = blockIdx.z / ksplit;
    const int split  = blockIdx.z - stream * ksplit;
    GArgs g = stream ? ga1 : ga0;
    float* Cf = g.Cf + (size_t)split * ROWS * Nc;
    const int tid = threadIdx.x, lane = tid & 31, warp = tid >> 5;
    const int wm = warp >> 2, wn = warp & 3;
    const int bm = blockIdx.y * 128, bn = blockIdx.x * 256;
    const uint32_t sbase = smem_u32(dsm);
    const int stBase = split * nstPer;

    const bf16* Ag = g.A + (size_t)bm * Kext;
    const bf16* Wg = g.W + (size_t)bn * Kext;

    int aRow[4], aSw[4], aC16[4];
    #pragma unroll
    for (int i = 0; i < 4; i++) {
        int idx = i * 256 + tid;
        aRow[i] = idx >> 3; aC16[i] = idx & 7;
        int off = aRow[i] * 128 + aC16[i] * 16;
        aSw[i] = off ^ ((aRow[i] & 7) << 4);
    }
    int bRow[8], bSw[8], bC16[8];
    #pragma unroll
    for (int i = 0; i < 8; i++) {
        int idx = i * 256 + tid;
        bRow[i] = idx >> 3; bC16[i] = idx & 7;
        int off = bRow[i] * 128 + bC16[i] * 16;
        bSw[i] = off ^ ((bRow[i] & 7) << 4);
    }

    const int la = lane & 15;
    const uint32_t khA = (lane >> 4) * 16;
    uint32_t aAdd[4], aXr[4];
    #pragma unroll
    for (int mi = 0; mi < 4; mi++) {
        int r = wm * 64 + mi * 16 + la;
        aAdd[mi] = r * 128; aXr[mi] = (r & 7) << 4;
    }
    // B: ldsm_x4 per nj-pair (16 n-rows x 16 k)
    const int bi = lane >> 3;
    const uint32_t khB = (bi & 1) * 16;
    uint32_t bAdd[4], bXr[4];
    #pragma unroll
    for (int njp = 0; njp < 4; njp++) {
        int r = wn * 64 + njp * 16 + (bi >> 1) * 8 + (lane & 7);
        bAdd[njp] = 16384u + r * 128; bXr[njp] = (r & 7) << 4;
    }

    float acc[4][8][4];
    #pragma unroll
    for (int mi = 0; mi < 4; mi++)
        #pragma unroll
        for (int nj = 0; nj < 8; nj++)
            #pragma unroll
            for (int q = 0; q < 4; q++) acc[mi][nj][q] = 0.f;

    auto load_stage = [&](int s, int stage) {
        if (s < nstPer) {
            uint32_t sb0 = sbase + (uint32_t)stage * STAGE_BYTES;
            #pragma unroll
            for (int sub = 0; sub < 2; sub++) {
                uint32_t sb = sb0 + (uint32_t)sub * SUB_BYTES;
                const int kofs = ((stBase + s) * 2 + sub) * 64;
                #pragma unroll
                for (int i = 0; i < 4; i++)
                    cp16(sb + aSw[i], Ag + (size_t)aRow[i] * Kext + kofs + aC16[i] * 8);
                #pragma unroll
                for (int i = 0; i < 8; i++)
                    cp16(sb + 16384u + bSw[i], Wg + (size_t)bRow[i] * Kext + kofs + bC16[i] * 8);
            }
        }
        CP_COMMIT();
    };

    load_stage(0, 0);
    load_stage(1, 1);

    for (int st = 0; st < nstPer; st++) {
        CP_WAIT1();
        __syncthreads();
        uint32_t base = sbase + (uint32_t)(st & 1) * STAGE_BYTES;
        #pragma unroll
        for (int sub = 0; sub < 2; sub++) {
            uint32_t sb = base + (uint32_t)sub * SUB_BYTES;
            #pragma unroll
            for (int ks = 0; ks < 4; ks++) {
                uint32_t afr[4][4], bfr[8][2];
                #pragma unroll
                for (int mi = 0; mi < 4; mi++)
                    ldsm_x4(afr[mi], sb + aAdd[mi] + (((uint32_t)ks * 32 + khA) ^ aXr[mi]));
                #pragma unroll
                for (int njp = 0; njp < 4; njp++) {
                    uint32_t t[4];
                    ldsm_x4(t, sb + bAdd[njp] + (((uint32_t)ks * 32 + khB) ^ bXr[njp]));
                    bfr[njp*2][0] = t[0];   bfr[njp*2][1] = t[1];
                    bfr[njp*2+1][0] = t[2]; bfr[njp*2+1][1] = t[3];
                }
                #pragma unroll
                for (int mi = 0; mi < 4; mi++)
                    #pragma unroll
                    for (int nj = 0; nj < 8; nj++)
                        hmma(acc[mi][nj], afr[mi], bfr[nj]);
            }
        }
        __syncthreads();
        load_stage(st + 2, st & 1);
    }

    const int gq = lane >> 2, tq = lane & 3;
    #pragma unroll
    for (int mi = 0; mi < 4; mi++) {
        #pragma unroll
        for (int nj = 0; nj < 8; nj++) {
            int co = bn + wn * 64 + nj * 8 + tq * 2;
            #pragma unroll
            for (int half = 0; half < 2; half++) {
                int row = bm + wm * 64 + mi * 16 + gq + half * 8;
                *reinterpret_cast<float2*>(Cf + (size_t)row * Nc + co) =
                    make_float2(acc[mi][nj][2 * half], acc[mi][nj][2 * half + 1]);
            }
        }
    }
}

// ---------------- combine1 ----------------
__global__ void combine1(const float* __restrict__ gp,
                         const float* __restrict__ b0, const float* __restrict__ b1,
                         bf16* __restrict__ C0, bf16* __restrict__ C1) {
    int i = blockIdx.x * 256 + threadIdx.x;
    int s = blockIdx.y;
    const size_t RH = (size_t)ROWS * H1v;
    const float* g = gp + (size_t)s * 3 * RH;
    bf16* C = s ? C1 : C0;
    const float* bias = s ? b1 : b0;
    float4 a = reinterpret_cast<const float4*>(g)[i];
    float4 b = reinterpret_cast<const float4*>(g + RH)[i];
    float4 c = reinterpret_cast<const float4*>(g + 2 * RH)[i];
    int row = (i * 4) / H1v, col = (i * 4) % H1v;
    float4 bb = *reinterpret_cast<const float4*>(bias + col);
    float v0 = fmaxf(a.x + b.x + c.x + bb.x, 0.f);
    float v1 = fmaxf(a.y + b.y + c.y + bb.y, 0.f);
    float v2 = fmaxf(a.z + b.z + c.z + bb.z, 0.f);
    float v3 = fmaxf(a.w + b.w + c.w + bb.w, 0.f);
    bf16 h0 = __float2bfloat16(v0), h1 = __float2bfloat16(v1);
    bf16 h2 = __float2bfloat16(v2), h3 = __float2bfloat16(v3);
    uint2 hw, lw;
    hw.x = packbf2(v0, v1); hw.y = packbf2(v2, v3);
    lw.x = packbf2(v0 - __bfloat162float(h0), v1 - __bfloat162float(h1));
    lw.y = packbf2(v2 - __bfloat162float(h2), v3 - __bfloat162float(h3));
    bf16* base = C + (size_t)row * (3 * H1v) + col;
    *reinterpret_cast<uint2*>(base) = hw;
    *reinterpret_cast<uint2*>(base + H1v) = hw;
    *reinterpret_cast<uint2*>(base + 2 * H1v) = lw;
}

// ---------------- combine2 ----------------
__global__ void combine2(const float* __restrict__ gp,
                         const float* __restrict__ b0, const float* __restrict__ b1,
                         const float* __restrict__ bnsc, const float* __restrict__ bnsh,
                         const float* __restrict__ rs,
                         float* __restrict__ h2a, float* __restrict__ h2b) {
    int i = blockIdx.x * 256 + threadIdx.x;
    int s = blockIdx.y;
    const size_t RH = (size_t)ROWS * H2v;
    const float* g = gp + (size_t)s * 2 * RH;
    const float* bias = s ? b1 : b0;
    float* outp = s ? h2b : h2a;
    float4 a = reinterpret_cast<const float4*>(g)[i];
    float4 b = reinterpret_cast<const float4*>(g + RH)[i];
    int row = (i * 4) / H2v, col = (i * 4) % H2v;
    int n = row % Nn;
    float sc = bnsc[s * Nn + n], sh = bnsh[s * Nn + n];
    float4 bb = *reinterpret_cast<const float4*>(bias + col);
    float4 rr = *reinterpret_cast<const float4*>(rs + s * H2v + col);
    float4 v;
    v.x = fmaxf(sc * (a.x + b.x) + sh * rr.x + bb.x, 0.f);
    v.y = fmaxf(sc * (a.y + b.y) + sh * rr.y + bb.y, 0.f);
    v.z = fmaxf(sc * (a.z + b.z) + sh * rr.z + bb.z, 0.f);
    v.w = fmaxf(sc * (a.w + b.w) + sh * rr.w + bb.w, 0.f);
    reinterpret_cast<float4*>(outp)[i] = v;
}

// ---------------- rowsum ----------------
__global__ void rowsum_kernel(const float* W0, const float* W1, int K, float* out) {
    int o = blockIdx.x, s = blockIdx.y;
    const float* W = s ? W1 : W0;
    float sum = 0.f;
    for (int k = threadIdx.x; k < K; k += blockDim.x) sum += W[(size_t)o * K + k];
    sum = blockReduceSum(sum);
    if (threadIdx.x == 0) out[s * H2v + o] = sum;
}

// ---------------- BN stats ----------------
__global__ void bnstats_ext_p1(const bf16* hA, const bf16* hB, int O, float* partial) {
    int n = blockIdx.x, s = blockIdx.y, bg = blockIdx.z;
    const bf16* h = s ? hB : hA;
    float sum = 0.f, ss = 0.f;
    for (int b = bg * 16; b < bg * 16 + 16; b++) {
        size_t off = (size_t)(b * Nn + n) * (3 * O);
        const __nv_bfloat162* ph = reinterpret_cast<const __nv_bfloat162*>(h + off);
        const __nv_bfloat162* pl = reinterpret_cast<const __nv_bfloat162*>(h + off + 2 * O);
        for (int o = threadIdx.x; o < O / 2; o += blockDim.x) {
            __nv_bfloat162 a = ph[o], c = pl[o];
            float v0 = __bfloat162float(a.x) + __bfloat162float(c.x);
            float v1 = __bfloat162float(a.y) + __bfloat162float(c.y);
            sum += v0 + v1; ss += v0 * v0 + v1 * v1;
        }
    }
    float2 r = blockReduce2(sum, ss);
    if (threadIdx.x == 0) {
        size_t pi = ((size_t)(s * Nn + n) * 8 + bg) * 2;
        partial[pi] = r.x; partial[pi + 1] = r.y;
    }
}

__global__ void bnstats_f32_p1(const float* hA, const float* hB, int O, float* partial) {
    int n = blockIdx.x, s = blockIdx.y, bg = blockIdx.z;
    const float* h = s ? hB : hA;
    float sum = 0.f, ss = 0.f;
    for (int b = bg * 16; b < bg * 16 + 16; b++) {
        const float4* row = reinterpret_cast<const float4*>(h + (size_t)(b * Nn + n) * O);
        for (int o = threadIdx.x; o < O / 4; o += blockDim.x) {
            float4 v = row[o];
            sum += v.x + v.y + v.z + v.w;
            ss += v.x * v.x + v.y * v.y + v.z * v.z + v.w * v.w;
        }
    }
    float2 r = blockReduce2(sum, ss);
    if (threadIdx.x == 0) {
        size_t pi = ((size_t)(s * Nn + n) * 8 + bg) * 2;
        partial[pi] = r.x; partial[pi + 1] = r.y;
    }
}

__global__ void bnstats_p2(const float* partial, int O,
                           const float* gA, const float* beA,
                           const float* gB, const float* beB,
                           float* sc, float* sh) {
    int i = blockIdx.x * blockDim.x + threadIdx.x;
    if (i >= 2 * Nn) return;
    int s = i / Nn, n = i - s * Nn;
    float sum = 0.f, ss = 0.f;
    for (int bg = 0; bg < 8; bg++) {
        size_t pi = ((size_t)i * 8 + bg) * 2;
        sum += partial[pi]; ss += partial[pi + 1];
    }
    const float* gg = s ? gB : gA;
    const float* be = s ? beB : beA;
    float cnt = (float)Bb * O, mean = sum / cnt;
    float var = ss / cnt - mean * mean;
    float scale = gg[n] * rsqrtf(var + 1e-5f);
    sc[s * Nn + n] = scale; sh[s * Nn + n] = be[n] - mean * scale;
}

// ---------------- scores ----------------
__global__ void scores_part_kernel(const float* h2a, const float* h2b,
                                   const float* sc, const float* sh, float* part) {
    int b = blockIdx.x;
    __shared__ float As[Nn][65], Bs[Nn][65];
    int tid = threadIdx.x, tx = tid & 15, ty = tid >> 4;
    float acc[4][4];
    #pragma unroll
    for (int i = 0; i < 4; i++)
        #pragma unroll
        for (int j = 0; j < 4; j++) acc[i][j] = 0.f;
    for (int h0 = 0; h0 < H2v; h0 += 64) {
        __syncthreads();
        for (int idx = tid; idx < Nn * 64; idx += 256) {
            int n = idx >> 6, kk = idx & 63;
            As[n][kk] = sc[2*Nn+n] * h2a[(size_t)(b*Nn+n)*H2v + h0 + kk] + sh[2*Nn+n];
            Bs[n][kk] = sc[3*Nn+n] * h2b[(size_t)(b*Nn+n)*H2v + h0 + kk] + sh[3*Nn+n];
        }
        __syncthreads();
        for (int kk = 0; kk < 64; kk++) {
            float ra[4], rb[4];
            #pragma unroll
            for (int i = 0; i < 4; i++) {
                int n = ty + 16 * i; ra[i] = (n < Nn) ? As[n][kk] : 0.f;
                int m = tx + 16 * i; rb[i] = (m < Nn) ? Bs[m][kk] : 0.f;
            }
            #pragma unroll
            for (int i = 0; i < 4; i++)
                #pragma unroll
                for (int j = 0; j < 4; j++) acc[i][j] += ra[i] * rb[j];
        }
    }
    #pragma unroll
    for (int i = 0; i < 4; i++)
        #pragma unroll
        for (int j = 0; j < 4; j++) {
            int n = ty + 16 * i, m = tx + 16 * j;
            if (n < Nn && m < Nn) part[(size_t)b * Nn * Nn + n * Nn + m] = acc[i][j];
        }
}
__global__ void scores_reduce_kernel(const float* part, float* scores) {
    int nm = blockIdx.x * 256 + threadIdx.x;
    if (nm >= Nn * Nn) return;
    float s = 0.f;
    for (int b = 0; b < Bb; b++) s += part[(size_t)b * Nn * Nn + nm];
    scores[nm] = s;
}

__global__ void mlin_kernel(const float* scores, const float* wlin, const float* blin,
                            const float* vmat, float* Mout) {
    int n = blockIdx.x;
    __shared__ float srow[Nn];
    if (threadIdx.x < Nn) srow[threadIdx.x] = scores[n * Nn + threadIdx.x];
    __syncthreads();
    int j = threadIdx.x;
    if (j < Nn) {
        float acc = blin[j];
        for (int m = 0; m < Nn; m++) acc += srow[m] * wlin[j * Nn + m];
        Mout[n * Nn + j] = vmat[n * Nn + j] + tanhf(acc);
    }
}

__global__ void topk_kernel(const float* M, float* vout, int* iout) {
    int mode = blockIdx.x, t = threadIdx.x;
    if (t >= Nn) return;
    float p[Nn], mx = -1e30f;
    for (int i = 0; i < Nn; i++) {
        float v = (mode == 0) ? M[t * Nn + i] : M[i * Nn + t];
        p[i] = v; mx = fmaxf(mx, v);
    }
    float sum = 0.f;
    for (int i = 0; i < Nn; i++) { p[i] = expf(p[i] - mx); sum += p[i]; }
    float inv = 1.f / sum;
    for (int i = 0; i < Nn; i++) p[i] *= inv;
    for (int k = 0; k < TOPKv; k++) {
        float bv = -1.f; int bi = 0;
        for (int i = 0; i < Nn; i++) if (p[i] > bv) { bv = p[i]; bi = i; }
        vout[mode * Nn * TOPKv + t * TOPKv + k] = bv;
        iout[mode * Nn * TOPKv + t * TOPKv + k] = bi;
        p[bi] = -2.f;
    }
}

// ---------------- fusion pass1 (plain) ----------------
__global__ __launch_bounds__(128)
void fusion_pass1(const float* __restrict__ base, const float* __restrict__ gath,
                  const float* __restrict__ vsel, const int* __restrict__ isel,
                  float* __restrict__ xout, float* __restrict__ partial)
{
    int dt = blockIdx.x, b = blockIdx.y, tid = threadIdx.x;
    __shared__ float4 tile4[Nn][32];
    __shared__ float sv[Nn * TOPKv];
    __shared__ int   si[Nn * TOPKv];

    for (int i = tid; i < Nn * TOPKv; i += 128) { sv[i] = vsel[i]; si[i] = isel[i]; }
    int dbase = dt * 128;
    for (int i = tid; i < Nn * 32; i += 128) {
        int m = i >> 5, q = i & 31;
        tile4[m][q] = reinterpret_cast<const float4*>(gath + (size_t)(b * Nn + m) * Dd + dbase)[q];
    }
    __syncthreads();

    int lane = tid & 31, w = tid >> 5;
    for (int n = w; n < Nn; n += 4) {
        float4 x = reinterpret_cast<const float4*>(base + (size_t)(b * Nn + n) * Dd + dbase)[lane];
        #pragma unroll
        for (int k = 0; k < TOPKv; k++) {
            float v = sv[n * TOPKv + k];
            float4 t = tile4[si[n * TOPKv + k]][lane];
            x.x += v * t.x; x.y += v * t.y; x.z += v * t.z; x.w += v * t.w;
        }
        reinterpret_cast<float4*>(xout + (size_t)(b * Nn + n) * Dd + dbase)[lane] = x;
        float s  = x.x + x.y + x.z + x.w;
        float ss = x.x * x.x + x.y * x.y + x.z * x.z + x.w * x.w;
        #pragma unroll
        for (int o = 16; o > 0; o >>= 1) {
            s  += __shfl_down_sync(0xffffffffu, s, o);
            ss += __shfl_down_sync(0xffffffffu, ss, o);
        }
        if (lane == 0) {
            size_t pi = ((size_t)(b * Nn + n) * 16 + dt) * 2;
            partial[pi] = s; partial[pi + 1] = ss;
        }
    }
}

// ---------------- fusion pass1 FUSED: also writes LN(gath) to out using prevPartial ----------------
__global__ __launch_bounds__(128)
void fusion_pass1_fused(const float* __restrict__ base, const float* __restrict__ gath,
                        const float* __restrict__ vsel, const int* __restrict__ isel,
                        float* __restrict__ xout, float* __restrict__ partial,
                        const float* __restrict__ prevPartial,
                        const float* __restrict__ ln_g, const float* __restrict__ ln_b,
                        float* __restrict__ out)
{
    int dt = blockIdx.x, b = blockIdx.y, tid = threadIdx.x;
    __shared__ float4 tile4[Nn][32];
    __shared__ float sv[Nn * TOPKv];
    __shared__ int   si[Nn * TOPKv];
    __shared__ float2 sstats[Nn];

    for (int i = tid; i < Nn * TOPKv; i += 128) { sv[i] = vsel[i]; si[i] = isel[i]; }
    int dbase = dt * 128;
    for (int i = tid; i < Nn * 32; i += 128) {
        int m = i >> 5, q = i & 31;
        tile4[m][q] = reinterpret_cast<const float4*>(gath + (size_t)(b * Nn + m) * Dd + dbase)[q];
    }
    // LN stats for gath rows (s1) from the completed previous partials
    for (int i = tid; i < Nn; i += 128) {
        float s = 0.f, q = 0.f;
        #pragma unroll
        for (int t = 0; t < 16; t++) {
            size_t pi = ((size_t)(b * Nn + i) * 16 + t) * 2;
            s += prevPartial[pi]; q += prevPartial[pi + 1];
        }
        float mean = s * (1.f / Dd);
        float var = fmaxf((q - s * mean) * (1.f / (Dd - 1)), 0.f);
        sstats[i] = make_float2(mean, 1.f / (sqrtf(var) + 1e-6f));
    }
    __syncthreads();

    int lane = tid & 31, w = tid >> 5;

    // write LN(s1) rows for this (b, dt) tile straight from smem
    {
        float4 gg = reinterpret_cast<const float4*>(ln_g + dbase)[lane];
        float4 bb = reinterpret_cast<const float4*>(ln_b + dbase)[lane];
        for (int m = w; m < Nn; m += 4) {
            float4 t = tile4[m][lane];
            float2 st = sstats[m];
            float4 o;
            o.x = gg.x * (t.x - st.x) * st.y + bb.x;
            o.y = gg.y * (t.y - st.x) * st.y + bb.y;
            o.z = gg.z * (t.z - st.x) * st.y + bb.z;
            o.w = gg.w * (t.w - st.x) * st.y + bb.w;
            reinterpret_cast<float4*>(out + (size_t)(b * (2 * Nn) + m) * Dd + dbase)[lane] = o;
        }
    }

    // gather/accumulate s2 rows
    for (int n = w; n < Nn; n += 4) {
        float4 x = reinterpret_cast<const float4*>(base + (size_t)(b * Nn + n) * Dd + dbase)[lane];
        #pragma unroll
        for (int k = 0; k < TOPKv; k++) {
            float v = sv[n * TOPKv + k];
            float4 t = tile4[si[n * TOPKv + k]][lane];
            x.x += v * t.x; x.y += v * t.y; x.z += v * t.z; x.w += v * t.w;
        }
        reinterpret_cast<float4*>(xout + (size_t)(b * Nn + n) * Dd + dbase)[lane] = x;
        float s  = x.x + x.y + x.z + x.w;
        float ss = x.x * x.x + x.y * x.y + x.z * x.z + x.w * x.w;
        #pragma unroll
        for (int o = 16; o > 0; o >>= 1) {
            s  += __shfl_down_sync(0xffffffffu, s, o);
            ss += __shfl_down_sync(0xffffffffu, ss, o);
        }
        if (lane == 0) {
            size_t pi = ((size_t)(b * Nn + n) * 16 + dt) * 2;
            partial[pi] = s; partial[pi + 1] = ss;
        }
    }
}

// ---------------- fusion apply (stats folded) ----------------
__global__ __launch_bounds__(256)
void fusion_apply(const float* __restrict__ x, const float* __restrict__ partial,
                  const float* __restrict__ ln_g, const float* __restrict__ ln_b,
                  float* __restrict__ out, int rowOff)
{
    int r = blockIdx.x;
    int b = r / Nn, n = r - b * Nn;
    __shared__ float sstat[2];
    if (threadIdx.x < 32) {
        float s = 0.f, q = 0.f;
        if (threadIdx.x < 16) {
            size_t pi = ((size_t)r * 16 + threadIdx.x) * 2;
            s = partial[pi]; q = partial[pi + 1];
        }
        #pragma unroll
        for (int o = 8; o > 0; o >>= 1) {
            s += __shfl_down_sync(0xffffffffu, s, o);
            q += __shfl_down_sync(0xffffffffu, q, o);
        }
        if (threadIdx.x == 0) {
            float mean = s * (1.f / Dd);
            float var = fmaxf((q - s * mean) * (1.f / (Dd - 1)), 0.f);
            sstat[0] = mean;
            sstat[1] = 1.f / (sqrtf(var) + 1e-6f);
        }
    }
    __syncthreads();
    float mean = sstat[0], inv = sstat[1];
    const float4* xv = reinterpret_cast<const float4*>(x + (size_t)r * Dd);
    const float4* gv = reinterpret_cast<const float4*>(ln_g);
    const float4* bv = reinterpret_cast<const float4*>(ln_b);
    float4* ov = reinterpret_cast<float4*>(out + (size_t)(b * (2 * Nn) + rowOff + n) * Dd);
    #pragma unroll
    for (int it = 0; it < 2; it++) {
        int d = it * 256 + threadIdx.x;
        float4 xx = xv[d], gg = gv[d], bb = bv[d];
        ov[d] = make_float4(gg.x * (xx.x - mean) * inv + bb.x,
                            gg.y * (xx.y - mean) * inv + bb.y,
                            gg.z * (xx.z - mean) * inv + bb.z,
                            gg.w * (xx.w - mean) * inv + bb.w);
    }
}

// ---------------- host ----------------
extern "C" void kernel_launch(void* const* d_in, const int* in_sizes, int n_in,
                              void* d_out, int out_size)
{
    const float *src1=(const float*)d_in[0], *src2=(const float*)d_in[1];
    const float *w0a=(const float*)d_in[2], *b0a=(const float*)d_in[3];
    const float *g0a=(const float*)d_in[4], *be0a=(const float*)d_in[5];
    const float *w0b=(const float*)d_in[6], *b0b=(const float*)d_in[7];
    const float *g0b=(const float*)d_in[8], *be0b=(const float*)d_in[9];
    const float *w1a=(const float*)d_in[10], *b1a=(const float*)d_in[11];
    const float *g1a=(const float*)d_in[12], *be1a=(const float*)d_in[13];
    const float *w1b=(const float*)d_in[14], *b1b=(const float*)d_in[15];
    const float *g1b=(const float*)d_in[16], *be1b=(const float*)d_in[17];
    const float *wlin=(const float*)d_in[18], *blin=(const float*)d_in[19];
    const float *ln_g=(const float*)d_in[20], *ln_b=(const float*)d_in[21];
    const float *vmat=(const float*)d_in[22];
    float* out = (float*)d_out;

    void* p;
    #define SYM(s,v,t) cudaGetSymbolAddress(&p,s); t v=(t)p;
    SYM(g_x1e,x1e,bf16*) SYM(g_x2e,x2e,bf16*)
    SYM(g_w0ae,w0ae,bf16*) SYM(g_w1ae,w1ae,bf16*)
    SYM(g_w0be,w0be,bf16*) SYM(g_w1be,w1be,bf16*)
    SYM(g_h1ae,h1ae,bf16*) SYM(g_h1be,h1be,bf16*)
    SYM(g_gp1,gp1,float*) SYM(g_gp2,gp2,float*)
    SYM(g_h2a,h2a,float*) SYM(g_h2b,h2b,float*)
    SYM(g_s1,s1,float*) SYM(g_s2,s2,float*)
    SYM(g_part,part,float*) SYM(g_scores,scores,float*) SYM(g_M,Mbuf,float*)
    SYM(g_bnsc,bnsc,float*) SYM(g_bnsh,bnsh,float*) SYM(g_rowsum,rsum,float*)
    SYM(g_bnpart,bnpart,float*)
    SYM(g_topv,topv,float*) SYM(g_topi,topi,int*)
    SYM(g_fpart,fpart,float*)
    #undef SYM

    cudaFuncSetAttribute(hmma_gemm, cudaFuncAttributeMaxDynamicSharedMemorySize, 196608);

    int n4 = ROWS * Dd / 4;
    cvt_ext3<<<dim3((n4+255)/256, 2), 256>>>(src1, src2, x1e, x2e, Dd/4, n4, 1);
    n4 = H1v * Dd / 4;
    cvt_ext3<<<dim3((n4+255)/256, 2), 256>>>(w0a, w1a, w0ae, w1ae, Dd/4, n4, 0);
    n4 = H2v * H1v / 4;
    cvt_ext3<<<dim3((n4+255)/256, 2), 256>>>(w0b, w1b, w0be, w1be, H1v/4, n4, 0);

    // launch #4: GEMM1 split-K=3
    GArgs a0 = { x1e, w0ae, gp1 };
    GArgs a1 = { x2e, w1ae, gp1 + (size_t)3 * ROWS * H1v };
    hmma_gemm<<<dim3(H1v/256, ROWS/128, 6), 256, 196608>>>(a0, a1, H1v, 3*Dd, 16, 3);

    combine1<<<dim3(ROWS*H1v/1024, 2), 256>>>(gp1, b0a, b1a, h1ae, h1be);

    rowsum_kernel<<<dim3(H2v,2), 256>>>(w0b, w1b, H1v, rsum);

    bnstats_ext_p1<<<dim3(Nn,2,8), 256>>>(h1ae, h1be, H1v, bnpart);
    bnstats_p2<<<1, 128>>>(bnpart, H1v, g0a, be0a, g1a, be1a, bnsc, bnsh);

    GArgs c0 = { h1ae, w0be, gp2 };
    GArgs c1 = { h1be, w1be, gp2 + (size_t)2 * ROWS * H2v };
    hmma_gemm<<<dim3(H2v/256, ROWS/128, 4), 256, 196608>>>(c0, c1, H2v, 3*H1v, 12, 2);

    combine2<<<dim3(ROWS*H2v/1024, 2), 256>>>(gp2, b0b, b1b, bnsc, bnsh, rsum, h2a, h2b);

    bnstats_f32_p1<<<dim3(Nn,2,8), 256>>>(h2a, h2b, H2v, bnpart);
    bnstats_p2<<<1, 128>>>(bnpart, H2v, g0b, be0b, g1b, be1b, bnsc + 2*Nn, bnsh + 2*Nn);

    scores_part_kernel<<<Bb, 256>>>(h2a, h2b, bnsc, bnsh, part);
    scores_reduce_kernel<<<(Nn*Nn+255)/256, 256>>>(part, scores);
    mlin_kernel<<<Nn, 64>>>(scores, wlin, blin, vmat, Mbuf);
    topk_kernel<<<2, 64>>>(Mbuf, topv, topi);

    // fusion: pass1 (s1), then fused pass (s2 + LN(s1) written from tile), then apply (s2)
    fusion_pass1<<<dim3(16, Bb), 128>>>(src1, src2, topv, topi, s1, fpart);
    fusion_pass1_fused<<<dim3(16, Bb), 128>>>(src2, s1, topv + Nn*TOPKv, topi + Nn*TOPKv,
                                              s2, fpart + ROWS*16*2,
                                              fpart, ln_g, ln_b, out);
    fusion_apply<<<ROWS, 256>>>(s2, fpart + ROWS*16*2, ln_g, ln_b, out, Nn);
}

// round 15
// speedup vs baseline: 1.0214x; 1.0214x over previous
#include <cuda_runtime.h>
#include <cuda_bf16.h>
#include <math.h>
#include <stdint.h>

#define Bb 128
#define Nn 49
#define Dd 2048
#define H1v 1024
#define H2v 512
#define ROWS (Bb*Nn)
#define TOPKv 20

typedef __nv_bfloat16 bf16;

// ---------------- static scratch ----------------
__device__ alignas(128) bf16 g_x1e[(size_t)ROWS*3*Dd];
__device__ alignas(128) bf16 g_x2e[(size_t)ROWS*3*Dd];
__device__ alignas(128) bf16 g_w0ae[(size_t)H1v*3*Dd];
__device__ alignas(128) bf16 g_w1ae[(size_t)H1v*3*Dd];
__device__ alignas(128) bf16 g_w0be[(size_t)H2v*3*H1v];
__device__ alignas(128) bf16 g_w1be[(size_t)H2v*3*H1v];
__device__ alignas(128) bf16 g_h1ae[(size_t)ROWS*3*H1v];
__device__ alignas(128) bf16 g_h1be[(size_t)ROWS*3*H1v];
__device__ alignas(128) float g_gp1[(size_t)6*ROWS*H1v];
__device__ alignas(128) float g_gp2[(size_t)4*ROWS*H2v];
__device__ alignas(128) float g_h2a[ROWS*H2v], g_h2b[ROWS*H2v];
__device__ alignas(128) float g_s1[ROWS*Dd], g_s2[ROWS*Dd];
__device__ float g_part[(size_t)Bb*Nn*Nn], g_scores[Nn*Nn], g_M[Nn*Nn];
__device__ float g_bnsc[4*Nn], g_bnsh[4*Nn], g_rowsum[2*H2v];
__device__ float g_rowstat[2*ROWS*2];
__device__ float g_topv[2*Nn*TOPKv];
__device__ int   g_topi[2*Nn*TOPKv];
__device__ float g_fpart[2*ROWS*16*2];

// ---------------- PTX helpers ----------------
__device__ __forceinline__ uint32_t smem_u32(const void* p) {
    uint32_t a;
    asm("{ .reg .u64 t; cvta.to.shared.u64 t, %1; cvt.u32.u64 %0, t; }" : "=r"(a) : "l"(p));
    return a;
}
__device__ __forceinline__ void cp16(uint32_t s, const void* g) {
    asm volatile("cp.async.cg.shared.global [%0], [%1], 16;" :: "r"(s), "l"(g));
}
#define CP_COMMIT() asm volatile("cp.async.commit_group;" ::: "memory")
#define CP_WAIT1()  asm volatile("cp.async.wait_group 1;" ::: "memory")

__device__ __forceinline__ void ldsm_x4(uint32_t (&r)[4], uint32_t a) {
    asm volatile("ldmatrix.sync.aligned.m8n8.x4.shared.b16 {%0,%1,%2,%3}, [%4];"
        : "=r"(r[0]), "=r"(r[1]), "=r"(r[2]), "=r"(r[3]) : "r"(a));
}
__device__ __forceinline__ void ldsm_x2(uint32_t (&r)[2], uint32_t a) {
    asm volatile("ldmatrix.sync.aligned.m8n8.x2.shared.b16 {%0,%1}, [%2];"
        : "=r"(r[0]), "=r"(r[1]) : "r"(a));
}
__device__ __forceinline__ void hmma(float (&d)[4], const uint32_t (&a)[4], const uint32_t (&b)[2]) {
    asm volatile("mma.sync.aligned.m16n8k16.row.col.f32.bf16.bf16.f32 "
        "{%0,%1,%2,%3},{%4,%5,%6,%7},{%8,%9},{%0,%1,%2,%3};"
        : "+f"(d[0]), "+f"(d[1]), "+f"(d[2]), "+f"(d[3])
        : "r"(a[0]), "r"(a[1]), "r"(a[2]), "r"(a[3]), "r"(b[0]), "r"(b[1]));
}
__device__ __forceinline__ uint32_t packbf2(float a, float b) {
    __nv_bfloat162 t = __floats2bfloat162_rn(a, b);
    return *reinterpret_cast<uint32_t*>(&t);
}

__device__ __forceinline__ float2 blockReduce2(float a, float b) {
    __shared__ float2 sb[8];
    int lane = threadIdx.x & 31, w = threadIdx.x >> 5;
    #pragma unroll
    for (int o = 16; o > 0; o >>= 1) {
        a += __shfl_down_sync(0xffffffffu, a, o);
        b += __shfl_down_sync(0xffffffffu, b, o);
    }
    __syncthreads();
    if (lane == 0) sb[w] = make_float2(a, b);
    __syncthreads();
    int nw = (blockDim.x + 31) >> 5;
    float2 r = make_float2(0.f, 0.f);
    #pragma unroll
    for (int i = 0; i < 8; i++) if (i < nw) { r.x += sb[i].x; r.y += sb[i].y; }
    return r;
}
__device__ __forceinline__ float blockReduceSum(float v) {
    float2 r = blockReduce2(v, 0.f);
    return r.x;
}

// ---------------- fp32 -> ext bf16 (two streams per launch) ----------------
__global__ void cvt_ext3(const float* __restrict__ x0, const float* __restrict__ x1,
                         bf16* __restrict__ y0, bf16* __restrict__ y1,
                         int K4, int n4, int kindA) {
    const float* x = blockIdx.y ? x1 : x0;
    bf16* y = blockIdx.y ? y1 : y0;
    int i = blockIdx.x * blockDim.x + threadIdx.x;
    if (i >= n4) return;
    int row = i / K4, k4 = i - row * K4;
    float4 v = reinterpret_cast<const float4*>(x)[i];
    bf16 h0 = __float2bfloat16(v.x), h1 = __float2bfloat16(v.y);
    bf16 h2 = __float2bfloat16(v.z), h3 = __float2bfloat16(v.w);
    uint2 hw, lw;
    hw.x = packbf2(v.x, v.y); hw.y = packbf2(v.z, v.w);
    lw.x = packbf2(v.x - __bfloat162float(h0), v.y - __bfloat162float(h1));
    lw.y = packbf2(v.z - __bfloat162float(h2), v.w - __bfloat162float(h3));
    bf16* base = y + (size_t)row * (12 * K4) + k4 * 4;
    *reinterpret_cast<uint2*>(base) = hw;
    if (kindA) {
        *reinterpret_cast<uint2*>(base + 4 * K4) = hw;
        *reinterpret_cast<uint2*>(base + 8 * K4) = lw;
    } else {
        *reinterpret_cast<uint2*>(base + 4 * K4) = lw;
        *reinterpret_cast<uint2*>(base + 8 * K4) = hw;
    }
}

// ---------------- HMMA GEMM: 128x256 CTA, split-K, raw fp32 partials (R13-exact inner loop) ----------------
struct GArgs {
    const bf16 *A, *W;
    float* Cf;
};

#define SUB_BYTES   49152u
#define STAGE_BYTES 98304u

__global__ __launch_bounds__(256, 1)
void hmma_gemm(GArgs ga0, GArgs ga1, int Nc, int Kext, int nstPer, int ksplit)
{
    extern __shared__ char dsm[];
    const int stream = blockIdx.z / ksplit;
    const int split  = blockIdx.z - stream * ksplit;
    GArgs g = stream ? ga1 : ga0;
    float* Cf = g.Cf + (size_t)split * ROWS * Nc;
    const int tid = threadIdx.x, lane = tid & 31, warp = tid >> 5;
    const int wm = warp >> 2, wn = warp & 3;
    const int bm = blockIdx.y * 128, bn = blockIdx.x * 256;
    const uint32_t sbase = smem_u32(dsm);
    const int stBase = split * nstPer;

    const bf16* Ag = g.A + (size_t)bm * Kext;
    const bf16* Wg = g.W + (size_t)bn * Kext;

    int aRow[4], aSw[4], aC16[4];
    #pragma unroll
    for (int i = 0; i < 4; i++) {
        int idx = i * 256 + tid;
        aRow[i] = idx >> 3; aC16[i] = idx & 7;
        int off = aRow[i] * 128 + aC16[i] * 16;
        aSw[i] = off ^ ((aRow[i] & 7) << 4);
    }
    int bRow[8], bSw[8], bC16[8];
    #pragma unroll
    for (int i = 0; i < 8; i++) {
        int idx = i * 256 + tid;
        bRow[i] = idx >> 3; bC16[i] = idx & 7;
        int off = bRow[i] * 128 + bC16[i] * 16;
        bSw[i] = off ^ ((bRow[i] & 7) << 4);
    }

    const int la = lane & 15;
    const uint32_t khA = (lane >> 4) * 16;
    uint32_t aAdd[4], aXr[4];
    #pragma unroll
    for (int mi = 0; mi < 4; mi++) {
        int r = wm * 64 + mi * 16 + la;
        aAdd[mi] = r * 128; aXr[mi] = (r & 7) << 4;
    }
    const uint32_t khB = ((lane >> 3) & 1) * 16;
    uint32_t bAdd[8], bXr[8];
    #pragma unroll
    for (int nj = 0; nj < 8; nj++) {
        int r = wn * 64 + nj * 8 + (lane & 7);
        bAdd[nj] = 16384u + r * 128; bXr[nj] = (r & 7) << 4;
    }

    float acc[4][8][4];
    #pragma unroll
    for (int mi = 0; mi < 4; mi++)
        #pragma unroll
        for (int nj = 0; nj < 8; nj++)
            #pragma unroll
            for (int q = 0; q < 4; q++) acc[mi][nj][q] = 0.f;

    auto load_stage = [&](int s, int stage) {
        if (s < nstPer) {
            uint32_t sb0 = sbase + (uint32_t)stage * STAGE_BYTES;
            #pragma unroll
            for (int sub = 0; sub < 2; sub++) {
                uint32_t sb = sb0 + (uint32_t)sub * SUB_BYTES;
                const int kofs = ((stBase + s) * 2 + sub) * 64;
                #pragma unroll
                for (int i = 0; i < 4; i++)
                    cp16(sb + aSw[i], Ag + (size_t)aRow[i] * Kext + kofs + aC16[i] * 8);
                #pragma unroll
                for (int i = 0; i < 8; i++)
                    cp16(sb + 16384u + bSw[i], Wg + (size_t)bRow[i] * Kext + kofs + bC16[i] * 8);
            }
        }
        CP_COMMIT();
    };

    load_stage(0, 0);
    load_stage(1, 1);

    for (int st = 0; st < nstPer; st++) {
        CP_WAIT1();
        __syncthreads();
        uint32_t base = sbase + (uint32_t)(st & 1) * STAGE_BYTES;
        #pragma unroll
        for (int sub = 0; sub < 2; sub++) {
            uint32_t sb = base + (uint32_t)sub * SUB_BYTES;
            #pragma unroll
            for (int ks = 0; ks < 4; ks++) {
                uint32_t afr[4][4], bfr[8][2];
                #pragma unroll
                for (int mi = 0; mi < 4; mi++)
                    ldsm_x4(afr[mi], sb + aAdd[mi] + (((uint32_t)ks * 32 + khA) ^ aXr[mi]));
                #pragma unroll
                for (int nj = 0; nj < 8; nj++)
                    ldsm_x2(bfr[nj], sb + bAdd[nj] + (((uint32_t)ks * 32 + khB) ^ bXr[nj]));
                #pragma unroll
                for (int mi = 0; mi < 4; mi++)
                    #pragma unroll
                    for (int nj = 0; nj < 8; nj++)
                        hmma(acc[mi][nj], afr[mi], bfr[nj]);
            }
        }
        __syncthreads();
        load_stage(st + 2, st & 1);
    }

    const int gq = lane >> 2, tq = lane & 3;
    #pragma unroll
    for (int mi = 0; mi < 4; mi++) {
        #pragma unroll
        for (int nj = 0; nj < 8; nj++) {
            int co = bn + wn * 64 + nj * 8 + tq * 2;
            #pragma unroll
            for (int half = 0; half < 2; half++) {
                int row = bm + wm * 64 + mi * 16 + gq + half * 8;
                *reinterpret_cast<float2*>(Cf + (size_t)row * Nc + co) =
                    make_float2(acc[mi][nj][2 * half], acc[mi][nj][2 * half + 1]);
            }
        }
    }
}

// ---------------- combine1 (row-per-block) + BN row stats ----------------
// One block per (row, stream): 256 thr x 4 elems = 1024 = H1v.
__global__ __launch_bounds__(256)
void combine1_row(const float* __restrict__ gp,
                  const float* __restrict__ b0, const float* __restrict__ b1,
                  bf16* __restrict__ C0, bf16* __restrict__ C1,
                  float* __restrict__ rowstat) {
    int r = blockIdx.x, s = blockIdx.y;
    const size_t RH = (size_t)ROWS * H1v;
    const float* g = gp + (size_t)s * 3 * RH + (size_t)r * H1v;
    bf16* C = (s ? C1 : C0) + (size_t)r * (3 * H1v);
    const float* bias = s ? b1 : b0;
    int col = threadIdx.x * 4;
    float4 a = *reinterpret_cast<const float4*>(g + col);
    float4 b = *reinterpret_cast<const float4*>(g + RH + col);
    float4 c = *reinterpret_cast<const float4*>(g + 2 * RH + col);
    float4 bb = *reinterpret_cast<const float4*>(bias + col);
    float v0 = fmaxf(a.x + b.x + c.x + bb.x, 0.f);
    float v1 = fmaxf(a.y + b.y + c.y + bb.y, 0.f);
    float v2 = fmaxf(a.z + b.z + c.z + bb.z, 0.f);
    float v3 = fmaxf(a.w + b.w + c.w + bb.w, 0.f);
    bf16 h0 = __float2bfloat16(v0), h1 = __float2bfloat16(v1);
    bf16 h2 = __float2bfloat16(v2), h3 = __float2bfloat16(v3);
    uint2 hw, lw;
    hw.x = packbf2(v0, v1); hw.y = packbf2(v2, v3);
    lw.x = packbf2(v0 - __bfloat162float(h0), v1 - __bfloat162float(h1));
    lw.y = packbf2(v2 - __bfloat162float(h2), v3 - __bfloat162float(h3));
    *reinterpret_cast<uint2*>(C + col) = hw;
    *reinterpret_cast<uint2*>(C + H1v + col) = hw;
    *reinterpret_cast<uint2*>(C + 2 * H1v + col) = lw;
    // exact values for BN stats: v = hi + lo (bf16 roundtrip), matching what GEMM2 consumes
    float e0 = __bfloat162float(h0) + __bfloat162float(__float2bfloat16(v0 - __bfloat162float(h0)));
    float e1 = __bfloat162float(h1) + __bfloat162float(__float2bfloat16(v1 - __bfloat162float(h1)));
    float e2 = __bfloat162float(h2) + __bfloat162float(__float2bfloat16(v2 - __bfloat162float(h2)));
    float e3 = __bfloat162float(h3) + __bfloat162float(__float2bfloat16(v3 - __bfloat162float(h3)));
    float ssum = e0 + e1 + e2 + e3;
    float ssq  = e0*e0 + e1*e1 + e2*e2 + e3*e3;
    float2 rr = blockReduce2(ssum, ssq);
    if (threadIdx.x == 0) {
        rowstat[((size_t)s * ROWS + r) * 2]     = rr.x;
        rowstat[((size_t)s * ROWS + r) * 2 + 1] = rr.y;
    }
}

// ---------------- combine2 (row-per-block) + BN row stats ----------------
__global__ __launch_bounds__(128)
void combine2_row(const float* __restrict__ gp,
                  const float* __restrict__ b0, const float* __restrict__ b1,
                  const float* __restrict__ bnsc, const float* __restrict__ bnsh,
                  const float* __restrict__ rs,
                  float* __restrict__ h2a, float* __restrict__ h2b,
                  float* __restrict__ rowstat) {
    int r = blockIdx.x, s = blockIdx.y;
    const size_t RH = (size_t)ROWS * H2v;
    const float* g = gp + (size_t)s * 2 * RH + (size_t)r * H2v;
    const float* bias = s ? b1 : b0;
    float* outp = (s ? h2b : h2a) + (size_t)r * H2v;
    int n = r % Nn;
    float sc = bnsc[s * Nn + n], sh = bnsh[s * Nn + n];
    int col = threadIdx.x * 4;
    float4 a = *reinterpret_cast<const float4*>(g + col);
    float4 b = *reinterpret_cast<const float4*>(g + RH + col);
    float4 bb = *reinterpret_cast<const float4*>(bias + col);
    float4 rr = *reinterpret_cast<const float4*>(rs + s * H2v + col);
    float4 v;
    v.x = fmaxf(sc * (a.x + b.x) + sh * rr.x + bb.x, 0.f);
    v.y = fmaxf(sc * (a.y + b.y) + sh * rr.y + bb.y, 0.f);
    v.z = fmaxf(sc * (a.z + b.z) + sh * rr.z + bb.z, 0.f);
    v.w = fmaxf(sc * (a.w + b.w) + sh * rr.w + bb.w, 0.f);
    *reinterpret_cast<float4*>(outp + col) = v;
    float sm = v.x + v.y + v.z + v.w;
    float sq = v.x*v.x + v.y*v.y + v.z*v.z + v.w*v.w;
    float2 rd = blockReduce2(sm, sq);
    if (threadIdx.x == 0) {
        rowstat[((size_t)s * ROWS + r) * 2]     = rd.x;
        rowstat[((size_t)s * ROWS + r) * 2 + 1] = rd.y;
    }
}

// ---------------- BN stats phase 2: reduce per-row stats over b ----------------
__global__ void bnstats_row_p2(const float* __restrict__ rowstat, int O,
                               const float* gA, const float* beA,
                               const float* gB, const float* beB,
                               float* sc, float* sh) {
    int i = blockIdx.x * blockDim.x + threadIdx.x;
    if (i >= 2 * Nn) return;
    int s = i / Nn, n = i - s * Nn;
    float sum = 0.f, ss = 0.f;
    for (int b = 0; b < Bb; b++) {
        size_t pi = ((size_t)s * ROWS + b * Nn + n) * 2;
        sum += rowstat[pi]; ss += rowstat[pi + 1];
    }
    const float* gg = s ? gB : gA;
    const float* be = s ? beB : beA;
    float cnt = (float)Bb * O, mean = sum / cnt;
    float var = ss / cnt - mean * mean;
    float scale = gg[n] * rsqrtf(var + 1e-5f);
    sc[s * Nn + n] = scale; sh[s * Nn + n] = be[n] - mean * scale;
}

// ---------------- rowsum ----------------
__global__ void rowsum_kernel(const float* W0, const float* W1, int K, float* out) {
    int o = blockIdx.x, s = blockIdx.y;
    const float* W = s ? W1 : W0;
    float sum = 0.f;
    for (int k = threadIdx.x; k < K; k += blockDim.x) sum += W[(size_t)o * K + k];
    sum = blockReduceSum(sum);
    if (threadIdx.x == 0) out[s * H2v + o] = sum;
}

// ---------------- scores ----------------
__global__ void scores_part_kernel(const float* h2a, const float* h2b,
                                   const float* sc, const float* sh, float* part) {
    int b = blockIdx.x;
    __shared__ float As[Nn][65], Bs[Nn][65];
    int tid = threadIdx.x, tx = tid & 15, ty = tid >> 4;
    float acc[4][4];
    #pragma unroll
    for (int i = 0; i < 4; i++)
        #pragma unroll
        for (int j = 0; j < 4; j++) acc[i][j] = 0.f;
    for (int h0 = 0; h0 < H2v; h0 += 64) {
        __syncthreads();
        for (int idx = tid; idx < Nn * 64; idx += 256) {
            int n = idx >> 6, kk = idx & 63;
            As[n][kk] = sc[2*Nn+n] * h2a[(size_t)(b*Nn+n)*H2v + h0 + kk] + sh[2*Nn+n];
            Bs[n][kk] = sc[3*Nn+n] * h2b[(size_t)(b*Nn+n)*H2v + h0 + kk] + sh[3*Nn+n];
        }
        __syncthreads();
        for (int kk = 0; kk < 64; kk++) {
            float ra[4], rb[4];
            #pragma unroll
            for (int i = 0; i < 4; i++) {
                int n = ty + 16 * i; ra[i] = (n < Nn) ? As[n][kk] : 0.f;
                int m = tx + 16 * i; rb[i] = (m < Nn) ? Bs[m][kk] : 0.f;
            }
            #pragma unroll
            for (int i = 0; i < 4; i++)
                #pragma unroll
                for (int j = 0; j < 4; j++) acc[i][j] += ra[i] * rb[j];
        }
    }
    #pragma unroll
    for (int i = 0; i < 4; i++)
        #pragma unroll
        for (int j = 0; j < 4; j++) {
            int n = ty + 16 * i, m = tx + 16 * j;
            if (n < Nn && m < Nn) part[(size_t)b * Nn * Nn + n * Nn + m] = acc[i][j];
        }
}
__global__ void scores_reduce_kernel(const float* part, float* scores) {
    int nm = blockIdx.x * 256 + threadIdx.x;
    if (nm >= Nn * Nn) return;
    float s = 0.f;
    for (int b = 0; b < Bb; b++) s += part[(size_t)b * Nn * Nn + nm];
    scores[nm] = s;
}

__global__ void mlin_kernel(const float* scores, const float* wlin, const float* blin,
                            const float* vmat, float* Mout) {
    int n = blockIdx.x;
    __shared__ float srow[Nn];
    if (threadIdx.x < Nn) srow[threadIdx.x] = scores[n * Nn + threadIdx.x];
    __syncthreads();
    int j = threadIdx.x;
    if (j < Nn) {
        float acc = blin[j];
        for (int m = 0; m < Nn; m++) acc += srow[m] * wlin[j * Nn + m];
        Mout[n * Nn + j] = vmat[n * Nn + j] + tanhf(acc);
    }
}

__global__ void topk_kernel(const float* M, float* vout, int* iout) {
    int mode = blockIdx.x, t = threadIdx.x;
    if (t >= Nn) return;
    float p[Nn], mx = -1e30f;
    for (int i = 0; i < Nn; i++) {
        float v = (mode == 0) ? M[t * Nn + i] : M[i * Nn + t];
        p[i] = v; mx = fmaxf(mx, v);
    }
    float sum = 0.f;
    for (int i = 0; i < Nn; i++) { p[i] = expf(p[i] - mx); sum += p[i]; }
    float inv = 1.f / sum;
    for (int i = 0; i < Nn; i++) p[i] *= inv;
    for (int k = 0; k < TOPKv; k++) {
        float bv = -1.f; int bi = 0;
        for (int i = 0; i < Nn; i++) if (p[i] > bv) { bv = p[i]; bi = i; }
        vout[mode * Nn * TOPKv + t * TOPKv + k] = bv;
        iout[mode * Nn * TOPKv + t * TOPKv + k] = bi;
        p[bi] = -2.f;
    }
}

// ---------------- fusion pass1 (plain) ----------------
__global__ __launch_bounds__(128)
void fusion_pass1(const float* __restrict__ base, const float* __restrict__ gath,
                  const float* __restrict__ vsel, const int* __restrict__ isel,
                  float* __restrict__ xout, float* __restrict__ partial)
{
    int dt = blockIdx.x, b = blockIdx.y, tid = threadIdx.x;
    __shared__ float4 tile4[Nn][32];
    __shared__ float sv[Nn * TOPKv];
    __shared__ int   si[Nn * TOPKv];

    for (int i = tid; i < Nn * TOPKv; i += 128) { sv[i] = vsel[i]; si[i] = isel[i]; }
    int dbase = dt * 128;
    for (int i = tid; i < Nn * 32; i += 128) {
        int m = i >> 5, q = i & 31;
        tile4[m][q] = reinterpret_cast<const float4*>(gath + (size_t)(b * Nn + m) * Dd + dbase)[q];
    }
    __syncthreads();

    int lane = tid & 31, w = tid >> 5;
    for (int n = w; n < Nn; n += 4) {
        float4 x = reinterpret_cast<const float4*>(base + (size_t)(b * Nn + n) * Dd + dbase)[lane];
        #pragma unroll
        for (int k = 0; k < TOPKv; k++) {
            float v = sv[n * TOPKv + k];
            float4 t = tile4[si[n * TOPKv + k]][lane];
            x.x += v * t.x; x.y += v * t.y; x.z += v * t.z; x.w += v * t.w;
        }
        reinterpret_cast<float4*>(xout + (size_t)(b * Nn + n) * Dd + dbase)[lane] = x;
        float s  = x.x + x.y + x.z + x.w;
        float ss = x.x * x.x + x.y * x.y + x.z * x.z + x.w * x.w;
        #pragma unroll
        for (int o = 16; o > 0; o >>= 1) {
            s  += __shfl_down_sync(0xffffffffu, s, o);
            ss += __shfl_down_sync(0xffffffffu, ss, o);
        }
        if (lane == 0) {
            size_t pi = ((size_t)(b * Nn + n) * 16 + dt) * 2;
            partial[pi] = s; partial[pi + 1] = ss;
        }
    }
}

// ---------------- fusion pass1 FUSED: also writes LN(gath) using prevPartial ----------------
__global__ __launch_bounds__(128)
void fusion_pass1_fused(const float* __restrict__ base, const float* __restrict__ gath,
                        const float* __restrict__ vsel, const int* __restrict__ isel,
                        float* __restrict__ xout, float* __restrict__ partial,
                        const float* __restrict__ prevPartial,
                        const float* __restrict__ ln_g, const float* __restrict__ ln_b,
                        float* __restrict__ out)
{
    int dt = blockIdx.x, b = blockIdx.y, tid = threadIdx.x;
    __shared__ float4 tile4[Nn][32];
    __shared__ float sv[Nn * TOPKv];
    __shared__ int   si[Nn * TOPKv];
    __shared__ float2 sstats[Nn];

    for (int i = tid; i < Nn * TOPKv; i += 128) { sv[i] = vsel[i]; si[i] = isel[i]; }
    int dbase = dt * 128;
    for (int i = tid; i < Nn * 32; i += 128) {
        int m = i >> 5, q = i & 31;
        tile4[m][q] = reinterpret_cast<const float4*>(gath + (size_t)(b * Nn + m) * Dd + dbase)[q];
    }
    for (int i = tid; i < Nn; i += 128) {
        float s = 0.f, q = 0.f;
        #pragma unroll
        for (int t = 0; t < 16; t++) {
            size_t pi = ((size_t)(b * Nn + i) * 16 + t) * 2;
            s += prevPartial[pi]; q += prevPartial[pi + 1];
        }
        float mean = s * (1.f / Dd);
        float var = fmaxf((q - s * mean) * (1.f / (Dd - 1)), 0.f);
        sstats[i] = make_float2(mean, 1.f / (sqrtf(var) + 1e-6f));
    }
    __syncthreads();

    int lane = tid & 31, w = tid >> 5;

    {
        float4 gg = reinterpret_cast<const float4*>(ln_g + dbase)[lane];
        float4 bb = reinterpret_cast<const float4*>(ln_b + dbase)[lane];
        for (int m = w; m < Nn; m += 4) {
            float4 t = tile4[m][lane];
            float2 st = sstats[m];
            float4 o;
            o.x = gg.x * (t.x - st.x) * st.y + bb.x;
            o.y = gg.y * (t.y - st.x) * st.y + bb.y;
            o.z = gg.z * (t.z - st.x) * st.y + bb.z;
            o.w = gg.w * (t.w - st.x) * st.y + bb.w;
            reinterpret_cast<float4*>(out + (size_t)(b * (2 * Nn) + m) * Dd + dbase)[lane] = o;
        }
    }

    for (int n = w; n < Nn; n += 4) {
        float4 x = reinterpret_cast<const float4*>(base + (size_t)(b * Nn + n) * Dd + dbase)[lane];
        #pragma unroll
        for (int k = 0; k < TOPKv; k++) {
            float v = sv[n * TOPKv + k];
            float4 t = tile4[si[n * TOPKv + k]][lane];
            x.x += v * t.x; x.y += v * t.y; x.z += v * t.z; x.w += v * t.w;
        }
        reinterpret_cast<float4*>(xout + (size_t)(b * Nn + n) * Dd + dbase)[lane] = x;
        float s  = x.x + x.y + x.z + x.w;
        float ss = x.x * x.x + x.y * x.y + x.z * x.z + x.w * x.w;
        #pragma unroll
        for (int o = 16; o > 0; o >>= 1) {
            s  += __shfl_down_sync(0xffffffffu, s, o);
            ss += __shfl_down_sync(0xffffffffu, ss, o);
        }
        if (lane == 0) {
            size_t pi = ((size_t)(b * Nn + n) * 16 + dt) * 2;
            partial[pi] = s; partial[pi + 1] = ss;
        }
    }
}

// ---------------- fusion apply (stats folded) ----------------
__global__ __launch_bounds__(256)
void fusion_apply(const float* __restrict__ x, const float* __restrict__ partial,
                  const float* __restrict__ ln_g, const float* __restrict__ ln_b,
                  float* __restrict__ out, int rowOff)
{
    int r = blockIdx.x;
    int b = r / Nn, n = r - b * Nn;
    __shared__ float sstat[2];
    if (threadIdx.x < 32) {
        float s = 0.f, q = 0.f;
        if (threadIdx.x < 16) {
            size_t pi = ((size_t)r * 16 + threadIdx.x) * 2;
            s = partial[pi]; q = partial[pi + 1];
        }
        #pragma unroll
        for (int o = 8; o > 0; o >>= 1) {
            s += __shfl_down_sync(0xffffffffu, s, o);
            q += __shfl_down_sync(0xffffffffu, q, o);
        }
        if (threadIdx.x == 0) {
            float mean = s * (1.f / Dd);
            float var = fmaxf((q - s * mean) * (1.f / (Dd - 1)), 0.f);
            sstat[0] = mean;
            sstat[1] = 1.f / (sqrtf(var) + 1e-6f);
        }
    }
    __syncthreads();
    float mean = sstat[0], inv = sstat[1];
    const float4* xv = reinterpret_cast<const float4*>(x + (size_t)r * Dd);
    const float4* gv = reinterpret_cast<const float4*>(ln_g);
    const float4* bv = reinterpret_cast<const float4*>(ln_b);
    float4* ov = reinterpret_cast<float4*>(out + (size_t)(b * (2 * Nn) + rowOff + n) * Dd);
    #pragma unroll
    for (int it = 0; it < 2; it++) {
        int d = it * 256 + threadIdx.x;
        float4 xx = xv[d], gg = gv[d], bb = bv[d];
        ov[d] = make_float4(gg.x * (xx.x - mean) * inv + bb.x,
                            gg.y * (xx.y - mean) * inv + bb.y,
                            gg.z * (xx.z - mean) * inv + bb.z,
                            gg.w * (xx.w - mean) * inv + bb.w);
    }
}

// ---------------- host ----------------
extern "C" void kernel_launch(void* const* d_in, const int* in_sizes, int n_in,
                              void* d_out, int out_size)
{
    const float *src1=(const float*)d_in[0], *src2=(const float*)d_in[1];
    const float *w0a=(const float*)d_in[2], *b0a=(const float*)d_in[3];
    const float *g0a=(const float*)d_in[4], *be0a=(const float*)d_in[5];
    const float *w0b=(const float*)d_in[6], *b0b=(const float*)d_in[7];
    const float *g0b=(const float*)d_in[8], *be0b=(const float*)d_in[9];
    const float *w1a=(const float*)d_in[10], *b1a=(const float*)d_in[11];
    const float *g1a=(const float*)d_in[12], *be1a=(const float*)d_in[13];
    const float *w1b=(const float*)d_in[14], *b1b=(const float*)d_in[15];
    const float *g1b=(const float*)d_in[16], *be1b=(const float*)d_in[17];
    const float *wlin=(const float*)d_in[18], *blin=(const float*)d_in[19];
    const float *ln_g=(const float*)d_in[20], *ln_b=(const float*)d_in[21];
    const float *vmat=(const float*)d_in[22];
    float* out = (float*)d_out;

    void* p;
    #define SYM(s,v,t) cudaGetSymbolAddress(&p,s); t v=(t)p;
    SYM(g_x1e,x1e,bf16*) SYM(g_x2e,x2e,bf16*)
    SYM(g_w0ae,w0ae,bf16*) SYM(g_w1ae,w1ae,bf16*)
    SYM(g_w0be,w0be,bf16*) SYM(g_w1be,w1be,bf16*)
    SYM(g_h1ae,h1ae,bf16*) SYM(g_h1be,h1be,bf16*)
    SYM(g_gp1,gp1,float*) SYM(g_gp2,gp2,float*)
    SYM(g_h2a,h2a,float*) SYM(g_h2b,h2b,float*)
    SYM(g_s1,s1,float*) SYM(g_s2,s2,float*)
    SYM(g_part,part,float*) SYM(g_scores,scores,float*) SYM(g_M,Mbuf,float*)
    SYM(g_bnsc,bnsc,float*) SYM(g_bnsh,bnsh,float*) SYM(g_rowsum,rsum,float*)
    SYM(g_rowstat,rowstat,float*)
    SYM(g_topv,topv,float*) SYM(g_topi,topi,int*)
    SYM(g_fpart,fpart,float*)
    #undef SYM

    cudaFuncSetAttribute(hmma_gemm, cudaFuncAttributeMaxDynamicSharedMemorySize, 196608);

    int n4 = ROWS * Dd / 4;
    cvt_ext3<<<dim3((n4+255)/256, 2), 256>>>(src1, src2, x1e, x2e, Dd/4, n4, 1);
    n4 = H1v * Dd / 4;
    cvt_ext3<<<dim3((n4+255)/256, 2), 256>>>(w0a, w1a, w0ae, w1ae, Dd/4, n4, 0);
    n4 = H2v * H1v / 4;
    cvt_ext3<<<dim3((n4+255)/256, 2), 256>>>(w0b, w1b, w0be, w1be, H1v/4, n4, 0);

    // launch #4: GEMM1 split-K=3
    GArgs a0 = { x1e, w0ae, gp1 };
    GArgs a1 = { x2e, w1ae, gp1 + (size_t)3 * ROWS * H1v };
    hmma_gemm<<<dim3(H1v/256, ROWS/128, 6), 256, 196608>>>(a0, a1, H1v, 3*Dd, 16, 3);

    // combine1 with fused BN row stats; then tiny phase-2
    combine1_row<<<dim3(ROWS, 2), 256>>>(gp1, b0a, b1a, h1ae, h1be, rowstat);
    rowsum_kernel<<<dim3(H2v,2), 256>>>(w0b, w1b, H1v, rsum);
    bnstats_row_p2<<<1, 128>>>(rowstat, H1v, g0a, be0a, g1a, be1a, bnsc, bnsh);

    GArgs c0 = { h1ae, w0be, gp2 };
    GArgs c1 = { h1be, w1be, gp2 + (size_t)2 * ROWS * H2v };
    hmma_gemm<<<dim3(H2v/256, ROWS/128, 4), 256, 196608>>>(c0, c1, H2v, 3*H1v, 12, 2);

    // combine2 with fused BN row stats; then tiny phase-2
    combine2_row<<<dim3(ROWS, 2), 128>>>(gp2, b0b, b1b, bnsc, bnsh, rsum, h2a, h2b, rowstat);
    bnstats_row_p2<<<1, 128>>>(rowstat, H2v, g0b, be0b, g1b, be1b, bnsc + 2*Nn, bnsh + 2*Nn);

    scores_part_kernel<<<Bb, 256>>>(h2a, h2b, bnsc, bnsh, part);
    scores_reduce_kernel<<<(Nn*Nn+255)/256, 256>>>(part, scores);
    mlin_kernel<<<Nn, 64>>>(scores, wlin, blin, vmat, Mbuf);
    topk_kernel<<<2, 64>>>(Mbuf, topv, topi);

    fusion_pass1<<<dim3(16, Bb), 128>>>(src1, src2, topv, topi, s1, fpart);
    fusion_pass1_fused<<<dim3(16, Bb), 128>>>(src2, s1, topv + Nn*TOPKv, topi + Nn*TOPKv,
                                              s2, fpart + ROWS*16*2,
                                              fpart, ln_g, ln_b, out);
    fusion_apply<<<ROWS, 256>>>(s2, fpart + ROWS*16*2, ln_g, ln_b, out, Nn);
}